// round 1
// baseline (speedup 1.0000x reference)
#include <cuda_runtime.h>

#define BB 2048
#define TMAX 2048

// scratch for the FIR pre-pass output: qx[t,i] = (x[t,i]-b_act)/max_current
__device__ float g_qx[TMAX * BB];

// ---------------------------------------------------------------------------
// Kernel A: FIR pre-pass.  qx[t,i] = (sum_k a[k]*cur[t-63+k, i] - b_act)/mc
// Block: 64 threads (one i-column each), tile of 64 t-outputs, smem-staged.
// 4-output register blocking -> 67 LDS + 256 FMA per group of 4 outputs.
// ---------------------------------------------------------------------------
__global__ void __launch_bounds__(64) fir_kernel(
    const float* __restrict__ cur,
    const float* __restrict__ a,
    const float* __restrict__ b_act,
    const float* __restrict__ max_cur,
    int T)
{
    __shared__ float sm[127][64];      // rows t0-63 .. t0+63
    const int li = threadIdx.x;        // 0..63
    const int i  = blockIdx.x * 64 + li;
    const int t0 = blockIdx.y * 64;

    float areg[64];
#pragma unroll
    for (int k = 0; k < 64; ++k) areg[k] = __ldg(&a[k]);
    const float bact   = __ldg(&b_act[0]);
    const float inv_mc = 1.0f / __ldg(&max_cur[0]);

#pragma unroll 1
    for (int rr = 0; rr < 127; ++rr) {
        int s = t0 - 63 + rr;
        sm[rr][li] = (s >= 0 && s < T) ? __ldg(&cur[(size_t)s * BB + i]) : 0.0f;
    }
    __syncthreads();

#pragma unroll 1
    for (int tt = 0; tt < 64; tt += 4) {
        float a0 = 0.f, a1 = 0.f, a2 = 0.f, a3 = 0.f;
#pragma unroll
        for (int rr = 0; rr < 67; ++rr) {
            float v = sm[tt + rr][li];
            if (rr <= 63)            a0 = fmaf(areg[rr],     v, a0);
            if (rr >= 1 && rr <= 64) a1 = fmaf(areg[rr - 1], v, a1);
            if (rr >= 2 && rr <= 65) a2 = fmaf(areg[rr - 2], v, a2);
            if (rr >= 3)             a3 = fmaf(areg[rr - 3], v, a3);
        }
        int t = t0 + tt;
        if (t + 0 < T) g_qx[(size_t)(t + 0) * BB + i] = (a0 - bact) * inv_mc;
        if (t + 1 < T) g_qx[(size_t)(t + 1) * BB + i] = (a1 - bact) * inv_mc;
        if (t + 2 < T) g_qx[(size_t)(t + 2) * BB + i] = (a2 - bact) * inv_mc;
        if (t + 3 < T) g_qx[(size_t)(t + 3) * BB + i] = (a3 - bact) * inv_mc;
    }
}

// ---------------------------------------------------------------------------
// Kernel B: serial recurrence.  2 lanes per batch element:
//   lane0 handles feedback taps j=1..32, lane1 taps j=33..64.
// Scatter formulation: producing f[t] scatters w[j]*f into future-partial
// registers; no per-step reduction except one shfl.xor combine of the halves.
// Slot alignment: lane r stores the partial for target tau in ring slot
// ((tau - 32*r) & 63), which makes all scatter indices lane-uniform; only the
// consume index differs (single FSEL per step).
// Time loop unrolled x64 so the 64-deep ring lives in registers.
// ---------------------------------------------------------------------------
__global__ void __launch_bounds__(32) rec_kernel(
    const float* __restrict__ b_lag,
    const float* __restrict__ poly_coeff,
    const float* __restrict__ max_cur,
    const float* __restrict__ max_fr,
    float* __restrict__ out,
    int T)
{
    const int lane = threadIdx.x;
    const int r    = lane & 1;                  // 0: taps 1..32, 1: taps 33..64
    const int e    = blockIdx.x * 16 + (lane >> 1);

    const float inv_mc = 1.0f / __ldg(&max_cur[0]);
    const float mfr    = __ldg(&max_fr[0]);
    float c0 = __ldg(&poly_coeff[0]); c0 *= c0;
    float c1 = __ldg(&poly_coeff[1]); c1 *= c1;
    float c2 = __ldg(&poly_coeff[2]); c2 *= c2;
    float c3 = __ldg(&poly_coeff[3]); c3 *= c3;
    const float cw = 1000.0f * inv_mc;

    // W[dd-1] = weight of f[t] toward target t+dd+32*r  (tap j = dd + 32*r)
    //         = cw * b_lag[64 - j]
    const int wbase = r ? 32 : 64;
    float W[32];
#pragma unroll
    for (int dd = 1; dd <= 32; ++dd) W[dd - 1] = cw * __ldg(&b_lag[wbase - dd]);

    float P[64];
#pragma unroll
    for (int p = 0; p < 64; ++p) P[p] = 0.0f;

    const bool writer = (r == 0);
    const float* qptr = g_qx + e;               // qx[0, e]
    float* optr = out + e;
    float qx_next = __ldg(qptr);                // prefetch t=0
    qptr += BB;                                  // points at t=1

    const float TWO_LOG2E = 2.8853900817779268f;   // 2*log2(e)

    for (int t0 = 0; t0 < T; t0 += 64) {
#pragma unroll
        for (int p = 0; p < 64; ++p) {
            const int t = t0 + p;
            // consume: lane0 reads slot p, lane1 reads slot p+32
            float ownA = P[p];
            float ownB = P[(p + 32) & 63];
            float own  = r ? ownB : ownA;
            float other = __shfl_xor_sync(0xffffffffu, own, 1);
            float xx = qx_next + own + other;

            // prefetch next qx (off critical path)
            qx_next = ((t + 1) < T) ? __ldg(qptr) : 0.0f;
            qptr += BB;

            // poly = c0 + c1*x + c2*x^2 + c3*x^3  (split-Horner, depth 8)
            float u  = xx * xx;
            float s1 = fmaf(c1, xx, c0);
            float s2 = fmaf(c3, xx, c2);
            float poly = fmaf(u, s2, s1);

            // tanh(poly) = 1 - 2/(exp2(poly*2log2e)+1)   (few-ulp accurate)
            float earg = poly * TWO_LOG2E;
            float ev;  asm("ex2.approx.f32 %0, %1;" : "=f"(ev) : "f"(earg));
            float den = ev + 1.0f;
            float rcp; asm("rcp.approx.f32 %0, %1;" : "=f"(rcp) : "f"(den));
            float th = fmaf(-2.0f, rcp, 1.0f);
            float f  = fmaxf(0.0f, mfr * th);

            if (writer && t < T) *optr = f;
            optr += BB;

            // scatter f into future partials: slots p+1..p+31 accumulate,
            // slot p+32 is the first contribution to its new target -> overwrite
#pragma unroll
            for (int dd = 1; dd <= 31; ++dd)
                P[(p + dd) & 63] = fmaf(W[dd - 1], f, P[(p + dd) & 63]);
            P[(p + 32) & 63] = W[31] * f;
        }
    }
}

// ---------------------------------------------------------------------------
extern "C" void kernel_launch(void* const* d_in, const int* in_sizes, int n_in,
                              void* d_out, int out_size)
{
    const float* currents = (const float*)d_in[0];
    const float* a        = (const float*)d_in[1];
    const float* b_lag    = (const float*)d_in[2];
    const float* poly     = (const float*)d_in[3];
    const float* b_act    = (const float*)d_in[4];
    const float* max_cur  = (const float*)d_in[5];
    const float* max_fr   = (const float*)d_in[6];
    float* out = (float*)d_out;

    const int T = in_sizes[0] / BB;   // 2000 for this problem

    dim3 gA(BB / 64, (T + 63) / 64);
    fir_kernel<<<gA, 64>>>(currents, a, b_act, max_cur, T);

    // 2 lanes per element, 16 elements per 32-thread block -> 128 blocks
    rec_kernel<<<BB / 16, 32>>>(b_lag, poly, max_cur, max_fr, out, T);
}

// round 2
// speedup vs baseline: 1.0308x; 1.0308x over previous
#include <cuda_runtime.h>

#define BB 2048
#define QROWS 2064   // up to TPAD=2048 plus prefetch margin; rows >= T stay zero

// scratch for FIR pre-pass output: qx[t,i] = (x[t,i]-b_act)/max_current
// device globals are zero-initialized; fir_kernel only writes rows t < T,
// so rows [T, QROWS) are always 0 -> tail steps compute harmless garbage.
__device__ float g_qx[QROWS * BB];

// ---------------------------------------------------------------------------
// Kernel A: FIR pre-pass.  qx[t,i] = (sum_k a[k]*cur[t-63+k, i] - b_act)/mc
// ---------------------------------------------------------------------------
__global__ void __launch_bounds__(64) fir_kernel(
    const float* __restrict__ cur,
    const float* __restrict__ a,
    const float* __restrict__ b_act,
    const float* __restrict__ max_cur,
    int T)
{
    __shared__ float sm[127][64];
    const int li = threadIdx.x;
    const int i  = blockIdx.x * 64 + li;
    const int t0 = blockIdx.y * 64;

    float areg[64];
#pragma unroll
    for (int k = 0; k < 64; ++k) areg[k] = __ldg(&a[k]);
    const float bact   = __ldg(&b_act[0]);
    const float inv_mc = 1.0f / __ldg(&max_cur[0]);

#pragma unroll 1
    for (int rr = 0; rr < 127; ++rr) {
        int s = t0 - 63 + rr;
        sm[rr][li] = (s >= 0 && s < T) ? __ldg(&cur[(size_t)s * BB + i]) : 0.0f;
    }
    __syncthreads();

#pragma unroll 1
    for (int tt = 0; tt < 64; tt += 4) {
        float a0 = 0.f, a1 = 0.f, a2 = 0.f, a3 = 0.f;
#pragma unroll
        for (int rr = 0; rr < 67; ++rr) {
            float v = sm[tt + rr][li];
            if (rr <= 63)            a0 = fmaf(areg[rr],     v, a0);
            if (rr >= 1 && rr <= 64) a1 = fmaf(areg[rr - 1], v, a1);
            if (rr >= 2 && rr <= 65) a2 = fmaf(areg[rr - 2], v, a2);
            if (rr >= 3)             a3 = fmaf(areg[rr - 3], v, a3);
        }
        int t = t0 + tt;
        if (t + 0 < T) g_qx[(size_t)(t + 0) * BB + i] = (a0 - bact) * inv_mc;
        if (t + 1 < T) g_qx[(size_t)(t + 1) * BB + i] = (a1 - bact) * inv_mc;
        if (t + 2 < T) g_qx[(size_t)(t + 2) * BB + i] = (a2 - bact) * inv_mc;
        if (t + 3 < T) g_qx[(size_t)(t + 3) * BB + i] = (a3 - bact) * inv_mc;
    }
}

// ---------------------------------------------------------------------------
// Kernel B: serial recurrence, 2 lanes per element (taps 1..32 / 33..64),
// scatter formulation with register ring P[64]; x64 unroll so indices are
// static. This round: fully branchless inner body, folded constants,
// 4-deep qx prefetch ring, predicated store via inline PTX.
// ---------------------------------------------------------------------------
__global__ void __launch_bounds__(32) rec_kernel(
    const float* __restrict__ b_lag,
    const float* __restrict__ poly_coeff,
    const float* __restrict__ max_cur,
    const float* __restrict__ max_fr,
    float* __restrict__ out,
    int T)
{
    const int lane = threadIdx.x;
    const int r    = lane & 1;
    const int e    = blockIdx.x * 16 + (lane >> 1);

    const float inv_mc = 1.0f / __ldg(&max_cur[0]);
    const float mfr    = __ldg(&max_fr[0]);
    const float TWO_LOG2E = 2.8853900817779268f;
    // fold 2*log2(e) into the squared coefficients: p2 = 2log2e * poly(x)
    float c0 = __ldg(&poly_coeff[0]); c0 = c0 * c0 * TWO_LOG2E;
    float c1 = __ldg(&poly_coeff[1]); c1 = c1 * c1 * TWO_LOG2E;
    float c2 = __ldg(&poly_coeff[2]); c2 = c2 * c2 * TWO_LOG2E;
    float c3 = __ldg(&poly_coeff[3]); c3 = c3 * c3 * TWO_LOG2E;
    const float cw      = 1000.0f * inv_mc;
    const float neg2mfr = -2.0f * mfr;

    // W[dd-1] = cw * b_lag[64 - (dd + 32*r)]
    const int wbase = r ? 32 : 64;
    float W[32];
#pragma unroll
    for (int dd = 1; dd <= 32; ++dd) W[dd - 1] = cw * __ldg(&b_lag[wbase - dd]);

    float P[64];
#pragma unroll
    for (int p = 0; p < 64; ++p) P[p] = 0.0f;

    // branchless store predicate: writer lanes compare t < T, others t < INT_MIN
    const int limit = (r == 0) ? T : (-2147483647 - 1);

    const float* qcol = g_qx + e;
    float q[4];
#pragma unroll
    for (int d = 0; d < 4; ++d) q[d] = __ldg(qcol + (size_t)d * BB);
    const float* qptr = qcol + (size_t)4 * BB;

    float* optr = out + e;
    const int TPAD = (T + 63) & ~63;   // tail steps run on zero qx rows, outputs predicated off

    for (int t0 = 0; t0 < TPAD; t0 += 64) {
#pragma unroll
        for (int p = 0; p < 64; ++p) {
            const int t = t0 + p;

            // consume: lane0 slot p, lane1 slot p+32 (FSEL, no branch)
            float own   = r ? P[(p + 32) & 63] : P[p];
            float other = __shfl_xor_sync(0xffffffffu, own, 1);
            float xx    = (own + other) + q[p & 3];

            // refill prefetch ring (t+4), unconditional: g_qx padded & zeroed
            q[p & 3] = __ldg(qptr);
            qptr += BB;

            // p2 = 2log2e*(c0 + c1 x + c2 x^2 + c3 x^3), split Horner
            float u  = xx * xx;
            float s1 = fmaf(c1, xx, c0);
            float s2 = fmaf(c3, xx, c2);
            float p2 = fmaf(u, s2, s1);

            // f = max(0, mfr * tanh(poly)) = max(0, mfr - 2mfr/(exp2(p2)+1))
            float ev;  asm("ex2.approx.f32 %0, %1;" : "=f"(ev) : "f"(p2));
            float den = ev + 1.0f;
            float rc;  asm("rcp.approx.f32 %0, %1;" : "=f"(rc) : "f"(den));
            float f = fmaxf(0.0f, fmaf(neg2mfr, rc, mfr));

            // predicated store (guaranteed branchless)
            asm volatile(
                "{\n\t.reg .pred p0;\n\t"
                "setp.lt.s32 p0, %1, %2;\n\t"
                "@p0 st.global.f32 [%0], %3;\n\t}"
                :: "l"(optr), "r"(t), "r"(limit), "f"(f) : "memory");
            optr += BB;

            // scatter: dd=1 first (it's the only scatter on the next-step chain)
            P[(p + 1) & 63] = fmaf(W[0], f, P[(p + 1) & 63]);
#pragma unroll
            for (int dd = 2; dd <= 31; ++dd)
                P[(p + dd) & 63] = fmaf(W[dd - 1], f, P[(p + dd) & 63]);
            P[(p + 32) & 63] = W[31] * f;   // first contribution: overwrite
        }
    }
}

// ---------------------------------------------------------------------------
extern "C" void kernel_launch(void* const* d_in, const int* in_sizes, int n_in,
                              void* d_out, int out_size)
{
    const float* currents = (const float*)d_in[0];
    const float* a        = (const float*)d_in[1];
    const float* b_lag    = (const float*)d_in[2];
    const float* poly     = (const float*)d_in[3];
    const float* b_act    = (const float*)d_in[4];
    const float* max_cur  = (const float*)d_in[5];
    const float* max_fr   = (const float*)d_in[6];
    float* out = (float*)d_out;

    const int T = in_sizes[0] / BB;   // 2000

    dim3 gA(BB / 64, (T + 63) / 64);
    fir_kernel<<<gA, 64>>>(currents, a, b_act, max_cur, T);

    rec_kernel<<<BB / 16, 32>>>(b_lag, poly, max_cur, max_fr, out, T);
}

// round 3
// speedup vs baseline: 1.0354x; 1.0045x over previous
#include <cuda_runtime.h>

#define BB 2048
#define QROWS 2080   // 2048 padded + prefetch margin; rows >= T stay zero

// FIR pre-pass output: qx[t,i] = (x[t,i]-b_act)/max_current. Zero-initialized;
// fir_kernel writes only rows t < T, so padding rows are always 0.
__device__ float g_qx[QROWS * BB];
// dump target for non-writer lanes' unconditional stores (never read)
__device__ float g_dump[64 * BB];

// ---------------------------------------------------------------------------
// Kernel A: FIR pre-pass (unchanged; ~5% of runtime)
// ---------------------------------------------------------------------------
__global__ void __launch_bounds__(64) fir_kernel(
    const float* __restrict__ cur,
    const float* __restrict__ a,
    const float* __restrict__ b_act,
    const float* __restrict__ max_cur,
    int T)
{
    __shared__ float sm[127][64];
    const int li = threadIdx.x;
    const int i  = blockIdx.x * 64 + li;
    const int t0 = blockIdx.y * 64;

    float areg[64];
#pragma unroll
    for (int k = 0; k < 64; ++k) areg[k] = __ldg(&a[k]);
    const float bact   = __ldg(&b_act[0]);
    const float inv_mc = 1.0f / __ldg(&max_cur[0]);

#pragma unroll 1
    for (int rr = 0; rr < 127; ++rr) {
        int s = t0 - 63 + rr;
        sm[rr][li] = (s >= 0 && s < T) ? __ldg(&cur[(size_t)s * BB + i]) : 0.0f;
    }
    __syncthreads();

#pragma unroll 1
    for (int tt = 0; tt < 64; tt += 4) {
        float a0 = 0.f, a1 = 0.f, a2 = 0.f, a3 = 0.f;
#pragma unroll
        for (int rr = 0; rr < 67; ++rr) {
            float v = sm[tt + rr][li];
            if (rr <= 63)            a0 = fmaf(areg[rr],     v, a0);
            if (rr >= 1 && rr <= 64) a1 = fmaf(areg[rr - 1], v, a1);
            if (rr >= 2 && rr <= 65) a2 = fmaf(areg[rr - 2], v, a2);
            if (rr >= 3)             a3 = fmaf(areg[rr - 3], v, a3);
        }
        int t = t0 + tt;
        if (t + 0 < T) g_qx[(size_t)(t + 0) * BB + i] = (a0 - bact) * inv_mc;
        if (t + 1 < T) g_qx[(size_t)(t + 1) * BB + i] = (a1 - bact) * inv_mc;
        if (t + 2 < T) g_qx[(size_t)(t + 2) * BB + i] = (a2 - bact) * inv_mc;
        if (t + 3 < T) g_qx[(size_t)(t + 3) * BB + i] = (a3 - bact) * inv_mc;
    }
}

// ---------------------------------------------------------------------------
// b64 pack/unpack + packed f32x2 FMA (FFMA2). These are rename-only in SASS.
// ---------------------------------------------------------------------------
#define UNPK(lo, hi, v) asm("mov.b64 {%0, %1}, %2;" : "=r"(lo), "=r"(hi) : "l"(v))
#define PK(v, lo, hi)   asm("mov.b64 %0, {%1, %2};" : "=l"(v) : "r"(lo), "r"(hi))
#define FMA2(acc, w, f2) asm("fma.rn.f32x2 %0, %1, %2, %0;" : "+l"(acc) : "l"(w), "l"(f2))

// ---------------------------------------------------------------------------
// One recurrence step, p = literal 0..63. Ring P2[32] = 64 float slots as b64
// pairs; slot s = half ((s)&1) of pair ((s)&63)>>1. Lane r in {0,1} owns taps
// dd+32r, dd=1..32; consume slot p (lane0) / p+32 (lane1); scatter f into
// slots p+1..p+32 (indices lane-uniform by construction).
// ---------------------------------------------------------------------------
#define STEP(p) { \
    unsigned lo0_, hi0_, lo1_, hi1_; \
    UNPK(lo0_, hi0_, P2[((p)&63)>>1]); \
    UNPK(lo1_, hi1_, P2[(((p)+32)&63)>>1]); \
    float own0_ = __uint_as_float((((p)&1) != 0) ? hi0_ : lo0_); \
    float own1_ = __uint_as_float((((p)&1) != 0) ? hi1_ : lo1_); \
    float own_  = r ? own1_ : own0_; \
    float oth_  = __shfl_xor_sync(0xffffffffu, own_, 1); \
    float xx_ = (own_ + oth_) + q[(p)&7]; \
    q[(p)&7] = __ldg(qb + (size_t)(p) * BB); \
    float u_  = xx_ * xx_; \
    float s1_ = fmaf(c1, xx_, c0); \
    float s2_ = fmaf(c3, xx_, c2); \
    float pv_ = fmaf(u_, s2_, s1_); \
    float ev_; asm("ex2.approx.f32 %0, %1;" : "=f"(ev_) : "f"(pv_)); \
    float dn_ = ev_ + 1.0f; \
    float rc_; asm("rcp.approx.f32 %0, %1;" : "=f"(rc_) : "f"(dn_)); \
    float f_ = fmaxf(0.0f, fmaf(neg2mfr, rc_, mfr)); \
    obase[(size_t)(p) * BB] = f_; \
    unsigned fu_ = __float_as_uint(f_); \
    unsigned long long ff2_; PK(ff2_, fu_, fu_); \
    if (((p) & 1) == 0) { \
        /* dd=1 first (critical for next step): slot p+1 = hi of pair p/2 */ \
        { unsigned l_, h_; UNPK(l_, h_, P2[(((p)+1)&63)>>1]); \
          float hh_ = fmaf(W0s, f_, __uint_as_float(h_)); \
          PK(P2[(((p)+1)&63)>>1], l_, __float_as_uint(hh_)); } \
        FMA2(P2[(((p)+ 2)&63)>>1], WO[ 0], ff2_); \
        FMA2(P2[(((p)+ 4)&63)>>1], WO[ 1], ff2_); \
        FMA2(P2[(((p)+ 6)&63)>>1], WO[ 2], ff2_); \
        FMA2(P2[(((p)+ 8)&63)>>1], WO[ 3], ff2_); \
        FMA2(P2[(((p)+10)&63)>>1], WO[ 4], ff2_); \
        FMA2(P2[(((p)+12)&63)>>1], WO[ 5], ff2_); \
        FMA2(P2[(((p)+14)&63)>>1], WO[ 6], ff2_); \
        FMA2(P2[(((p)+16)&63)>>1], WO[ 7], ff2_); \
        FMA2(P2[(((p)+18)&63)>>1], WO[ 8], ff2_); \
        FMA2(P2[(((p)+20)&63)>>1], WO[ 9], ff2_); \
        FMA2(P2[(((p)+22)&63)>>1], WO[10], ff2_); \
        FMA2(P2[(((p)+24)&63)>>1], WO[11], ff2_); \
        FMA2(P2[(((p)+26)&63)>>1], WO[12], ff2_); \
        FMA2(P2[(((p)+28)&63)>>1], WO[13], ff2_); \
        FMA2(P2[(((p)+30)&63)>>1], WO[14], ff2_); \
        /* dd=32 overwrite: slot p+32 = lo of its pair, hi preserved */ \
        { unsigned l_, h_; UNPK(l_, h_, P2[(((p)+32)&63)>>1]); \
          float ll_ = W31s * f_; (void)l_; \
          PK(P2[(((p)+32)&63)>>1], __float_as_uint(ll_), h_); } \
    } else { \
        /* zero hi half (slot p+32) so the last packed FMA acts as overwrite */ \
        { unsigned l_, h_; UNPK(l_, h_, P2[(((p)+32)&63)>>1]); (void)h_; \
          PK(P2[(((p)+32)&63)>>1], l_, 0u); } \
        FMA2(P2[(((p)+ 1)&63)>>1], WE[ 0], ff2_); \
        FMA2(P2[(((p)+ 3)&63)>>1], WE[ 1], ff2_); \
        FMA2(P2[(((p)+ 5)&63)>>1], WE[ 2], ff2_); \
        FMA2(P2[(((p)+ 7)&63)>>1], WE[ 3], ff2_); \
        FMA2(P2[(((p)+ 9)&63)>>1], WE[ 4], ff2_); \
        FMA2(P2[(((p)+11)&63)>>1], WE[ 5], ff2_); \
        FMA2(P2[(((p)+13)&63)>>1], WE[ 6], ff2_); \
        FMA2(P2[(((p)+15)&63)>>1], WE[ 7], ff2_); \
        FMA2(P2[(((p)+17)&63)>>1], WE[ 8], ff2_); \
        FMA2(P2[(((p)+19)&63)>>1], WE[ 9], ff2_); \
        FMA2(P2[(((p)+21)&63)>>1], WE[10], ff2_); \
        FMA2(P2[(((p)+23)&63)>>1], WE[11], ff2_); \
        FMA2(P2[(((p)+25)&63)>>1], WE[12], ff2_); \
        FMA2(P2[(((p)+27)&63)>>1], WE[13], ff2_); \
        FMA2(P2[(((p)+29)&63)>>1], WE[14], ff2_); \
        FMA2(P2[(((p)+31)&63)>>1], WE[15], ff2_); \
    } \
}

#define S4(b)  STEP(b) STEP((b)+1) STEP((b)+2) STEP((b)+3)
#define S16(b) S4(b) S4((b)+4) S4((b)+8) S4((b)+12)
#define S64()  S16(0) S16(16) S16(32) S16(48)

// ---------------------------------------------------------------------------
__global__ void __launch_bounds__(32) rec_kernel(
    const float* __restrict__ b_lag,
    const float* __restrict__ poly_coeff,
    const float* __restrict__ max_cur,
    const float* __restrict__ max_fr,
    float* __restrict__ out,
    int T)
{
    const int lane = threadIdx.x;
    const int r    = lane & 1;
    const int e    = blockIdx.x * 16 + (lane >> 1);

    const float inv_mc = 1.0f / __ldg(&max_cur[0]);
    const float mfr    = __ldg(&max_fr[0]);
    const float TWO_LOG2E = 2.8853900817779268f;   // 2*log2(e), folded into coeffs
    float c0 = __ldg(&poly_coeff[0]); c0 = c0 * c0 * TWO_LOG2E;
    float c1 = __ldg(&poly_coeff[1]); c1 = c1 * c1 * TWO_LOG2E;
    float c2 = __ldg(&poly_coeff[2]); c2 = c2 * c2 * TWO_LOG2E;
    float c3 = __ldg(&poly_coeff[3]); c3 = c3 * c3 * TWO_LOG2E;
    const float cw      = 1000.0f * inv_mc;
    const float neg2mfr = -2.0f * mfr;

    // W[dd-1] = cw * b_lag[wbase - dd], dd = 1..32
    const int wbase = r ? 32 : 64;
    float Wsc[32];
#pragma unroll
    for (int dd = 1; dd <= 32; ++dd) Wsc[dd - 1] = cw * __ldg(&b_lag[wbase - dd]);

    // packed weights: WE[k]=(W[2k],W[2k+1]) for odd p; WO[k]=(W[2k+1],W[2k+2]) for even p
    unsigned long long WE[16], WO[15];
#pragma unroll
    for (int k = 0; k < 16; ++k)
        PK(WE[k], __float_as_uint(Wsc[2*k]), __float_as_uint(Wsc[2*k+1]));
#pragma unroll
    for (int k = 0; k < 15; ++k)
        PK(WO[k], __float_as_uint(Wsc[2*k+1]), __float_as_uint(Wsc[2*k+2]));
    const float W0s = Wsc[0], W31s = Wsc[31];

    unsigned long long P2[32];
#pragma unroll
    for (int k = 0; k < 32; ++k) P2[k] = 0ull;

    // 8-deep qx prefetch ring
    float q[8];
#pragma unroll
    for (int d = 0; d < 8; ++d) q[d] = __ldg(g_qx + e + (size_t)d * BB);

    // writer lanes -> out, others -> dump (unconditional stores, no predicate)
    float* obase = (r == 0) ? (out + e) : (g_dump + e);
    const size_t ostep = (r == 0) ? (size_t)64 * BB : 0;

    const int nfull = T >> 6;
    for (int blk = 0; blk < nfull; ++blk) {
        const float* qb = g_qx + e + (size_t)(blk * 64 + 8) * BB;
        S64()
        obase += ostep;
    }

    // ---- tail: T mod 64 steps, slow dynamic-index path (<= 63 steps) ----
    const int t0tail = nfull * 64;
    const int tail   = T - t0tail;
    if (tail > 0) {
        float ring[64];
#pragma unroll
        for (int k = 0; k < 32; ++k) {
            unsigned lo, hi; UNPK(lo, hi, P2[k]);
            ring[2*k]   = __uint_as_float(lo);
            ring[2*k+1] = __uint_as_float(hi);
        }
#pragma unroll 1
        for (int tt = 0; tt < tail; ++tt) {
            int t = t0tail + tt;
            int p = t & 63;
            float own = r ? ring[(p + 32) & 63] : ring[p];
            float oth = __shfl_xor_sync(0xffffffffu, own, 1);
            float xx  = own + oth + __ldg(g_qx + e + (size_t)t * BB);
            float u_  = xx * xx;
            float s1_ = fmaf(c1, xx, c0);
            float s2_ = fmaf(c3, xx, c2);
            float pv  = fmaf(u_, s2_, s1_);
            float ev; asm("ex2.approx.f32 %0, %1;" : "=f"(ev) : "f"(pv));
            float dn = ev + 1.0f;
            float rc; asm("rcp.approx.f32 %0, %1;" : "=f"(rc) : "f"(dn));
            float f = fmaxf(0.0f, fmaf(neg2mfr, rc, mfr));
            if (r == 0) out[(size_t)t * BB + e] = f;
#pragma unroll 1
            for (int dd = 1; dd <= 31; ++dd)
                ring[(p + dd) & 63] = fmaf(Wsc[dd - 1], f, ring[(p + dd) & 63]);
            ring[(p + 32) & 63] = Wsc[31] * f;
        }
    }
}

// ---------------------------------------------------------------------------
extern "C" void kernel_launch(void* const* d_in, const int* in_sizes, int n_in,
                              void* d_out, int out_size)
{
    const float* currents = (const float*)d_in[0];
    const float* a        = (const float*)d_in[1];
    const float* b_lag    = (const float*)d_in[2];
    const float* poly     = (const float*)d_in[3];
    const float* b_act    = (const float*)d_in[4];
    const float* max_cur  = (const float*)d_in[5];
    const float* max_fr   = (const float*)d_in[6];
    float* out = (float*)d_out;

    const int T = in_sizes[0] / BB;   // 2000

    dim3 gA(BB / 64, (T + 63) / 64);
    fir_kernel<<<gA, 64>>>(currents, a, b_act, max_cur, T);

    rec_kernel<<<BB / 16, 32>>>(b_lag, poly, max_cur, max_fr, out, T);
}

// round 4
// speedup vs baseline: 1.3360x; 1.2903x over previous
#include <cuda_runtime.h>

#define BB 2048
#define QROWS 2080   // 2048 padded + prefetch margin; rows >= T stay zero

// FIR pre-pass output: qx[t,i] = (x[t,i]-b_act)/max_current. Zero-initialized;
// fir_kernel writes only rows t < T, so padding rows are always 0.
__device__ float g_qx[QROWS * BB];
// dump target for non-writer lanes' unconditional stores (never read)
__device__ float g_dump[64 * BB];

// ---------------------------------------------------------------------------
// Kernel A: FIR pre-pass (unchanged)
// ---------------------------------------------------------------------------
__global__ void __launch_bounds__(64) fir_kernel(
    const float* __restrict__ cur,
    const float* __restrict__ a,
    const float* __restrict__ b_act,
    const float* __restrict__ max_cur,
    int T)
{
    __shared__ float sm[127][64];
    const int li = threadIdx.x;
    const int i  = blockIdx.x * 64 + li;
    const int t0 = blockIdx.y * 64;

    float areg[64];
#pragma unroll
    for (int k = 0; k < 64; ++k) areg[k] = __ldg(&a[k]);
    const float bact   = __ldg(&b_act[0]);
    const float inv_mc = 1.0f / __ldg(&max_cur[0]);

#pragma unroll 1
    for (int rr = 0; rr < 127; ++rr) {
        int s = t0 - 63 + rr;
        sm[rr][li] = (s >= 0 && s < T) ? __ldg(&cur[(size_t)s * BB + i]) : 0.0f;
    }
    __syncthreads();

#pragma unroll 1
    for (int tt = 0; tt < 64; tt += 4) {
        float a0 = 0.f, a1 = 0.f, a2 = 0.f, a3 = 0.f;
#pragma unroll
        for (int rr = 0; rr < 67; ++rr) {
            float v = sm[tt + rr][li];
            if (rr <= 63)            a0 = fmaf(areg[rr],     v, a0);
            if (rr >= 1 && rr <= 64) a1 = fmaf(areg[rr - 1], v, a1);
            if (rr >= 2 && rr <= 65) a2 = fmaf(areg[rr - 2], v, a2);
            if (rr >= 3)             a3 = fmaf(areg[rr - 3], v, a3);
        }
        int t = t0 + tt;
        if (t + 0 < T) g_qx[(size_t)(t + 0) * BB + i] = (a0 - bact) * inv_mc;
        if (t + 1 < T) g_qx[(size_t)(t + 1) * BB + i] = (a1 - bact) * inv_mc;
        if (t + 2 < T) g_qx[(size_t)(t + 2) * BB + i] = (a2 - bact) * inv_mc;
        if (t + 3 < T) g_qx[(size_t)(t + 3) * BB + i] = (a3 - bact) * inv_mc;
    }
}

// ---------------------------------------------------------------------------
// Kernel B: 4 lanes per element, systolic hand-off recurrence.
// Lane r owns taps j = 16r+1 .. 16r+16 with a 16-slot ring R.
// R slot for target tau holds the partial sum of taps from lanes >= r and is
// RELEASED at step tau-16r: lane0's released value is the complete feedback
// y(t); lanes 1..3 hand theirs down one lane via shfl_down (width 4), where it
// seeds the receiving lane's overwrite slot. All ring indices are literals
// (macro-unrolled x16), keeping everything in registers (~60 live regs).
// ---------------------------------------------------------------------------
#define STEP(p) { \
    float val_ = R[(p)&15]; \
    float hU_  = __shfl_down_sync(0xffffffffu, val_, 1, 4); \
    float U_   = (r == 3) ? 0.0f : hU_; \
    float y_   = __shfl_sync(0xffffffffu, val_, 0, 4); \
    float xx_  = y_ + q[(p)&7]; \
    q[(p)&7]   = __ldg(qb + (size_t)(p) * BB); \
    float u_   = xx_ * xx_; \
    float s1_  = fmaf(c1, xx_, c0); \
    float s2_  = fmaf(c3, xx_, c2); \
    float pv_  = fmaf(u_, s2_, s1_); \
    float ev_; asm("ex2.approx.f32 %0, %1;" : "=f"(ev_) : "f"(pv_)); \
    float dn_  = ev_ + 1.0f; \
    float rc_; asm("rcp.approx.f32 %0, %1;" : "=f"(rc_) : "f"(dn_)); \
    float f_   = fmaxf(0.0f, fmaf(neg2mfr, rc_, mfr)); \
    obase[(size_t)(p) * BB] = f_; \
    R[((p)+ 1)&15] = fmaf(W[ 0], f_, R[((p)+ 1)&15]); \
    R[((p)+ 2)&15] = fmaf(W[ 1], f_, R[((p)+ 2)&15]); \
    R[((p)+ 3)&15] = fmaf(W[ 2], f_, R[((p)+ 3)&15]); \
    R[((p)+ 4)&15] = fmaf(W[ 3], f_, R[((p)+ 4)&15]); \
    R[((p)+ 5)&15] = fmaf(W[ 4], f_, R[((p)+ 5)&15]); \
    R[((p)+ 6)&15] = fmaf(W[ 5], f_, R[((p)+ 6)&15]); \
    R[((p)+ 7)&15] = fmaf(W[ 6], f_, R[((p)+ 7)&15]); \
    R[((p)+ 8)&15] = fmaf(W[ 7], f_, R[((p)+ 8)&15]); \
    R[((p)+ 9)&15] = fmaf(W[ 8], f_, R[((p)+ 9)&15]); \
    R[((p)+10)&15] = fmaf(W[ 9], f_, R[((p)+10)&15]); \
    R[((p)+11)&15] = fmaf(W[10], f_, R[((p)+11)&15]); \
    R[((p)+12)&15] = fmaf(W[11], f_, R[((p)+12)&15]); \
    R[((p)+13)&15] = fmaf(W[12], f_, R[((p)+13)&15]); \
    R[((p)+14)&15] = fmaf(W[13], f_, R[((p)+14)&15]); \
    R[((p)+15)&15] = fmaf(W[14], f_, R[((p)+15)&15]); \
    R[(p)&15]      = fmaf(W[15], f_, U_); \
}

#define S16() STEP(0) STEP(1) STEP(2) STEP(3) STEP(4) STEP(5) STEP(6) STEP(7) \
              STEP(8) STEP(9) STEP(10) STEP(11) STEP(12) STEP(13) STEP(14) STEP(15)

__global__ void __launch_bounds__(128) rec_kernel(
    const float* __restrict__ b_lag,
    const float* __restrict__ poly_coeff,
    const float* __restrict__ max_cur,
    const float* __restrict__ max_fr,
    float* __restrict__ out,
    int T)
{
    const int lane = threadIdx.x;
    const int r    = lane & 3;                       // lane within 4-lane group
    const int e    = blockIdx.x * 32 + (lane >> 2);  // element index

    const float inv_mc = 1.0f / __ldg(&max_cur[0]);
    const float mfr    = __ldg(&max_fr[0]);
    const float TWO_LOG2E = 2.8853900817779268f;     // 2*log2(e) folded into coeffs
    float c0 = __ldg(&poly_coeff[0]); c0 = c0 * c0 * TWO_LOG2E;
    float c1 = __ldg(&poly_coeff[1]); c1 = c1 * c1 * TWO_LOG2E;
    float c2 = __ldg(&poly_coeff[2]); c2 = c2 * c2 * TWO_LOG2E;
    float c3 = __ldg(&poly_coeff[3]); c3 = c3 * c3 * TWO_LOG2E;
    const float cw      = 1000.0f * inv_mc;
    const float neg2mfr = -2.0f * mfr;

    // lane r owns taps j = 16r+d (d=1..16); weight = cw * b_lag[64 - j]
    float W[16];
#pragma unroll
    for (int d = 1; d <= 16; ++d) W[d - 1] = cw * __ldg(&b_lag[64 - 16 * r - d]);

    float R[16];
#pragma unroll
    for (int k = 0; k < 16; ++k) R[k] = 0.0f;

    // 8-deep qx prefetch ring
    float q[8];
#pragma unroll
    for (int d = 0; d < 8; ++d) q[d] = __ldg(g_qx + e + (size_t)d * BB);

    // lane0 of each group writes real output; others store to dump (no branches)
    float* obase = (r == 0) ? (out + e) : (g_dump + e);
    const size_t ostep = (r == 0) ? (size_t)16 * BB : 0;

    const int nfull = T >> 4;
    for (int blk = 0; blk < nfull; ++blk) {
        const float* qb = g_qx + e + (size_t)(blk * 16 + 8) * BB;
        S16()
        obase += ostep;
    }

    // ---- generic tail (T mod 16 steps): slow dynamic-index path ----
    const int t0tail = nfull * 16;
    const int tail   = T - t0tail;
    if (tail > 0) {
        float ringD[16];
#pragma unroll
        for (int k = 0; k < 16; ++k) ringD[k] = R[k];
#pragma unroll 1
        for (int tt = 0; tt < tail; ++tt) {
            int t = t0tail + tt;
            int p = t & 15;
            float val = ringD[p];
            float hU  = __shfl_down_sync(0xffffffffu, val, 1, 4);
            float U   = (r == 3) ? 0.0f : hU;
            float y   = __shfl_sync(0xffffffffu, val, 0, 4);
            float xx  = y + __ldg(g_qx + e + (size_t)t * BB);
            float u_  = xx * xx;
            float s1_ = fmaf(c1, xx, c0);
            float s2_ = fmaf(c3, xx, c2);
            float pv  = fmaf(u_, s2_, s1_);
            float ev; asm("ex2.approx.f32 %0, %1;" : "=f"(ev) : "f"(pv));
            float dn = ev + 1.0f;
            float rc; asm("rcp.approx.f32 %0, %1;" : "=f"(rc) : "f"(dn));
            float f = fmaxf(0.0f, fmaf(neg2mfr, rc, mfr));
            if (r == 0) out[(size_t)t * BB + e] = f;
#pragma unroll 1
            for (int d = 1; d <= 15; ++d)
                ringD[(p + d) & 15] = fmaf(W[d - 1], f, ringD[(p + d) & 15]);
            ringD[p] = fmaf(W[15], f, U);
        }
    }
}

// ---------------------------------------------------------------------------
extern "C" void kernel_launch(void* const* d_in, const int* in_sizes, int n_in,
                              void* d_out, int out_size)
{
    const float* currents = (const float*)d_in[0];
    const float* a        = (const float*)d_in[1];
    const float* b_lag    = (const float*)d_in[2];
    const float* poly     = (const float*)d_in[3];
    const float* b_act    = (const float*)d_in[4];
    const float* max_cur  = (const float*)d_in[5];
    const float* max_fr   = (const float*)d_in[6];
    float* out = (float*)d_out;

    const int T = in_sizes[0] / BB;   // 2000

    dim3 gA(BB / 64, (T + 63) / 64);
    fir_kernel<<<gA, 64>>>(currents, a, b_act, max_cur, T);

    // 4 lanes/element, 32 elements per 128-thread block -> 64 blocks,
    // 1 block per SM, each warp alone on its SMSP.
    rec_kernel<<<BB / 32, 128>>>(b_lag, poly, max_cur, max_fr, out, T);
}